// round 10
// baseline (speedup 1.0000x reference)
#include <cuda_runtime.h>
#include <cuda_fp16.h>
#include <math.h>
#include <stdint.h>

#define KC   256
#define D    512
#define NLOW 130816

// Dense L in fp16, natural orientation: g_Lh[k][d][e] = L_k[d][e].
__device__ __half g_Lh[(size_t)KC * D * D];
// X in fp16.
__device__ __half g_Xh[(size_t)1024 * D];
// wL[k][e] = sum_d w_k[d] * Lh_k[d][e]  (fp32)
__device__ float g_wL[(size_t)KC * D];
// Per-e-block partial squared sums: g_part[j][b][k]
__device__ float g_part[(size_t)4 * 1024 * KC];

__device__ __forceinline__ uint32_t smem_u32(const void* p) {
    uint32_t a;
    asm("{ .reg .u64 t; cvta.to.shared.u64 t, %1; cvt.u32.u64 %0, t; }"
        : "=r"(a) : "l"(p));
    return a;
}
__device__ __forceinline__ void cpasync16(uint32_t dst, const void* src) {
    asm volatile("cp.async.cg.shared.global [%0], [%1], 16;"
                 :: "r"(dst), "l"(src) : "memory");
}
#define LDSM4(r0, r1, r2, r3, addr) \
    asm volatile("ldmatrix.sync.aligned.m8n8.x4.shared.b16 {%0,%1,%2,%3}, [%4];" \
                 : "=r"(r0), "=r"(r1), "=r"(r2), "=r"(r3) : "r"(addr))
#define LDSM4T(r0, r1, r2, r3, addr) \
    asm volatile("ldmatrix.sync.aligned.m8n8.x4.trans.shared.b16 {%0,%1,%2,%3}, [%4];" \
                 : "=r"(r0), "=r"(r1), "=r"(r2), "=r"(r3) : "r"(addr))

#define MBAR_INIT(mbar, cnt) \
    asm volatile("mbarrier.init.shared.b64 [%0], %1;" \
                 :: "r"((uint32_t)(mbar)), "r"((uint32_t)(cnt)) : "memory")
#define MBAR_ARRIVE(mbar) \
    asm volatile("mbarrier.arrive.shared.b64 _, [%0];" \
                 :: "r"((uint32_t)(mbar)) : "memory")
#define CP_ASYNC_MBAR_ARRIVE(mbar) \
    asm volatile("cp.async.mbarrier.arrive.noinc.shared.b64 [%0];" \
                 :: "r"((uint32_t)(mbar)) : "memory")
#define MBAR_WAIT(mbar, parity) do { \
    uint32_t _m = (uint32_t)(mbar); \
    uint32_t _p = (uint32_t)(parity); \
    uint32_t _done; \
    asm volatile("{\n\t.reg .pred p;\n\t" \
        "mbarrier.try_wait.parity.acquire.cta.shared::cta.b64 p, [%1], %2;\n\t" \
        "selp.b32 %0, 1, 0, p;\n\t}" \
        : "=r"(_done) : "r"(_m), "r"(_p) : "memory"); \
    if (!_done) { \
        asm volatile("{\n\t.reg .pred P1;\n\t" \
            "WL_%=:\n\t" \
            "mbarrier.try_wait.parity.acquire.cta.shared::cta.b64 P1, [%0], %1, 0x989680;\n\t" \
            "@P1 bra.uni WD_%=;\n\t" \
            "bra.uni WL_%=;\n\t" \
            "WD_%=:\n\t}" \
            :: "r"(_m), "r"(_p) : "memory"); \
    } \
} while(0)

// ---------------------------------------------------------------------------
// build_Lh: streaming expansion of packed L into fp16 [k][d][e], MLP=8.
// ---------------------------------------------------------------------------
__global__ void __launch_bounds__(256)
build_Lh(const float* __restrict__ diags, const float* __restrict__ lower) {
    const size_t i = (size_t)blockIdx.x * 256 + threadIdx.x;  // KC*D*64
    const int ep = ((int)(i & 63)) << 3;         // e..e+7
    const size_t kd = i >> 6;                    // k*D + d
    const int d  = (int)(kd & 511);
    const int kk = (int)(kd >> 9);
    if (d < ((ep >> 7) << 7)) return;            // never-read region
    const float* rowp = lower + (size_t)kk * NLOW + (((size_t)d * (d - 1)) >> 1);
    float v[8];
#pragma unroll
    for (int t = 0; t < 8; ++t) {
        const int e = ep + t;
        v[t] = (e < d) ? rowp[e] : 0.f;
    }
    if (d >= ep && d < ep + 8) { float t = diags[kd]; v[d - ep] = t * t; }
    uint4 u;
    __half2 h;
    h = __floats2half2_rn(v[0], v[1]); u.x = *(uint32_t*)&h;
    h = __floats2half2_rn(v[2], v[3]); u.y = *(uint32_t*)&h;
    h = __floats2half2_rn(v[4], v[5]); u.z = *(uint32_t*)&h;
    h = __floats2half2_rn(v[6], v[7]); u.w = *(uint32_t*)&h;
    *(uint4*)((char*)g_Lh + (kd * D + ep) * 2) = u;
}

// ---------------------------------------------------------------------------
__global__ void __launch_bounds__(256)
build_Xh(const float* __restrict__ X) {
    const int i = (blockIdx.x * 256 + threadIdx.x) * 4;   // 1024*512
    float4 x = *(const float4*)&X[i];
    __half2 h0 = __floats2half2_rn(x.x, x.y);
    __half2 h1 = __floats2half2_rn(x.z, x.w);
    *(uint2*)((char*)g_Xh + i * 2) = make_uint2(*(uint32_t*)&h0, *(uint32_t*)&h1);
}

// ---------------------------------------------------------------------------
// build_wL: wL[k][e] = sum_{d} w[d] * Lh[k][d][e].  grid (KC, 2), 256 thr.
// ---------------------------------------------------------------------------
__global__ void __launch_bounds__(256)
build_wL(const float* __restrict__ W) {
    __shared__ float ws[512];
    const int k = blockIdx.x, tid = threadIdx.x;
    ws[tid]       = W[(size_t)k * D + tid];
    ws[tid + 256] = W[(size_t)k * D + 256 + tid];
    __syncthreads();
    const int e = blockIdx.y * 256 + tid;
    const __half* Lk = g_Lh + (size_t)k * D * D;
    float s0 = 0.f, s1 = 0.f;
    const int dstart = (e >> 7) << 7;            // (512 - dstart) % 16 == 0
#pragma unroll 1
    for (int d = dstart; d < D; d += 16) {
#pragma unroll
        for (int t = 0; t < 16; t += 2) {
            s0 += ws[d + t]     * __half2float(Lk[(size_t)(d + t) * D + e]);
            s1 += ws[d + t + 1] * __half2float(Lk[(size_t)(d + t + 1) * D + e]);
        }
    }
    g_wL[(size_t)k * D + e] = s0 + s1;
}

// ---------------------------------------------------------------------------
// Main GEMM: Q = Xh @ Lh block; epilogue squares (Q - wL[e]) and row-reduces.
// K-chunks of 64, 3 SMEM stages, split-phase mbarrier pipeline (no per-chunk
// __syncthreads). A: 128x64 halfs stride 144 B. B: 64x128 halfs stride 272 B.
// ---------------------------------------------------------------------------
#define ROFF    0
#define WLOFF   1024
#define MBAROFF 1536
#define STG0    1600
#define ASZ     18432                          /* 128 * 144 */
#define BSZ     17408                          /* 64 * 272 */
#define STGSZ   (ASZ + BSZ)                    /* 35840 */
#define SMEMSZ  (STG0 + 3 * STGSZ)             /* 109120 */

__global__ void __launch_bounds__(256, 2)
gml2_mma() {
    extern __shared__ char smem[];
    const int tid = threadIdx.x;
    const int wid = tid >> 5, lid = tid & 31;
    const int b0 = blockIdx.x * 128;
    const int k  = blockIdx.y;
    const int j  = blockIdx.z;
    const int e0 = j << 7;
    const int nc = 8 - (j << 1);              // K-chunks of 64 (>= 2)

    const uint32_t sbase = smem_u32(smem);
    const uint32_t mb    = sbase + MBAROFF;   // full[3] @ +0, empty[3] @ +24
    float* wLs = (float*)(smem + WLOFF);

    if (tid == 0) {
#pragma unroll
        for (int s = 0; s < 3; ++s) {
            MBAR_INIT(mb + s * 8, 256);        // full[s]
            MBAR_INIT(mb + 24 + s * 8, 256);   // empty[s]
        }
    }
    if (tid < 128) wLs[tid] = g_wL[(size_t)k * D + e0 + tid];
    __syncthreads();

    const __half* Bk = g_Lh + (size_t)k * D * D;   // [d][e]
    const __half* Ab = g_Xh + (size_t)b0 * D;

#define ISSUE_CHUNK(cc, st) do {                                            \
        const int d0_ = e0 + (cc) * 64;                                     \
        const uint32_t as_ = sbase + STG0 + (st) * STGSZ;                   \
        const uint32_t bs_ = as_ + ASZ;                                     \
        _Pragma("unroll")                                                   \
        for (int it = 0; it < 4; ++it) {  /* A: 128 rows x 8 segs */        \
            const int idx = it * 256 + tid;                                 \
            const int row = idx >> 3, seg = idx & 7;                        \
            cpasync16(as_ + row * 144 + seg * 16,                           \
                      Ab + (size_t)row * D + d0_ + seg * 8);                \
        }                                                                   \
        _Pragma("unroll")                                                   \
        for (int it = 0; it < 4; ++it) {  /* B: 64 rows x 16 segs */        \
            const int idx = it * 256 + tid;                                 \
            const int rl = idx >> 4, seg = idx & 15;                        \
            cpasync16(bs_ + rl * 272 + seg * 16,                            \
                      Bk + (size_t)(d0_ + rl) * D + e0 + seg * 8);          \
        }                                                                   \
    } while (0)

    // ---- prologue: fill all 3 stages (chunks 0..2), arrive on full[s]
#pragma unroll
    for (int p = 0; p < 3; ++p) {
        if (p < nc) {
            ISSUE_CHUNK(p, p);
            CP_ASYNC_MBAR_ARRIVE(mb + p * 8);
        }
    }

    float acc[2][8][4];
#pragma unroll
    for (int mt = 0; mt < 2; ++mt)
#pragma unroll
        for (int nt = 0; nt < 8; ++nt)
#pragma unroll
            for (int q = 0; q < 4; ++q) acc[mt][nt][q] = 0.f;

    const int m0 = (wid & 3) * 32, n0 = (wid >> 2) * 64;
    const uint32_t aL = sbase + STG0 + (m0 + (lid & 15)) * 144 + (lid >> 4) * 16;
    const uint32_t bL = sbase + STG0 + ASZ +
                        (lid & 15) * 272 + (lid >> 4) * 16 + n0 * 2;

    for (int c = 0; c < nc; ++c) {
        const int st = c % 3;
        const int ph = (c / 3) & 1;
        const uint32_t fullb  = mb + st * 8;
        const uint32_t emptyb = mb + 24 + st * 8;

        MBAR_WAIT(fullb, ph);                 // copies for chunk c landed

        if (!(n0 == 64 && c == 0)) {
            const uint32_t aB = aL + st * STGSZ;
            const uint32_t bB = bL + st * STGSZ;
#pragma unroll
            for (int ks = 0; ks < 4; ++ks) {
                uint32_t a[2][4], b[8][2];
#pragma unroll
                for (int mt = 0; mt < 2; ++mt)
                    LDSM4(a[mt][0], a[mt][1], a[mt][2], a[mt][3],
                          aB + mt * (16 * 144) + ks * 32);
#pragma unroll
                for (int nt2 = 0; nt2 < 4; ++nt2)
                    LDSM4T(b[nt2 * 2][0], b[nt2 * 2][1],
                           b[nt2 * 2 + 1][0], b[nt2 * 2 + 1][1],
                           bB + ks * (16 * 272) + nt2 * 32);
#pragma unroll
                for (int mt = 0; mt < 2; ++mt)
#pragma unroll
                    for (int nt = 0; nt < 8; ++nt)
                        asm volatile(
                            "mma.sync.aligned.m16n8k16.row.col.f32.f16.f16.f32 "
                            "{%0,%1,%2,%3},{%4,%5,%6,%7},{%8,%9},{%0,%1,%2,%3};"
                            : "+f"(acc[mt][nt][0]), "+f"(acc[mt][nt][1]),
                              "+f"(acc[mt][nt][2]), "+f"(acc[mt][nt][3])
                            : "r"(a[mt][0]), "r"(a[mt][1]),
                              "r"(a[mt][2]), "r"(a[mt][3]),
                              "r"(b[nt][0]), "r"(b[nt][1]));
            }
        }

        MBAR_ARRIVE(emptyb);                  // done reading stage st (use c/3)

        if (c + 3 < nc) {                     // refill stage st with chunk c+3
            MBAR_WAIT(emptyb, ph);            // all 256 threads done with c
            ISSUE_CHUNK(c + 3, st);
            CP_ASYNC_MBAR_ARRIVE(fullb);
        }
    }
#undef ISSUE_CHUNK

    // ---- epilogue: subtract wL, square, row-reduce
    const int gq = lid >> 2, tg = lid & 3;
    float q[4];
#pragma unroll
    for (int mt = 0; mt < 2; ++mt) {
        float s0 = 0.f, s1 = 0.f;
#pragma unroll
        for (int nt = 0; nt < 8; ++nt) {
            const int c0 = n0 + nt * 8 + tg * 2;
            const float wl0 = wLs[c0], wl1 = wLs[c0 + 1];
            float p0 = acc[mt][nt][0] - wl0;
            float p1 = acc[mt][nt][1] - wl1;
            float p2 = acc[mt][nt][2] - wl0;
            float p3 = acc[mt][nt][3] - wl1;
            s0 += p0 * p0 + p1 * p1;
            s1 += p2 * p2 + p3 * p3;
        }
        q[mt * 2 + 0] = s0;   // row m0 + 16*mt + gq
        q[mt * 2 + 1] = s1;   // row m0 + 16*mt + gq + 8
    }
#pragma unroll
    for (int i = 0; i < 4; ++i) {
        q[i] += __shfl_xor_sync(0xffffffffu, q[i], 1);
        q[i] += __shfl_xor_sync(0xffffffffu, q[i], 2);
    }
    float* red = (float*)(smem + ROFF);
    __syncthreads();
    if (tg == 0) {
        const int wn = wid >> 2;
        const int rr = m0 + gq;
        red[wn * 128 + rr +  0] = q[0];
        red[wn * 128 + rr +  8] = q[1];
        red[wn * 128 + rr + 16] = q[2];
        red[wn * 128 + rr + 24] = q[3];
    }
    __syncthreads();
    if (tid < 128) {
        float s = red[tid] + red[128 + tid];
        g_part[((size_t)j * 1024 + b0 + tid) * KC + k] = s;
    }
}

// ---------------------------------------------------------------------------
__global__ void finalize(float* __restrict__ out) {
    const size_t idx = (size_t)blockIdx.x * 256 + threadIdx.x;  // 1024*256
    float s = g_part[idx] + g_part[262144 + idx] +
              g_part[2 * 262144 + idx] + g_part[3 * 262144 + idx];
    out[idx] = sqrtf(s);
}

// ---------------------------------------------------------------------------
extern "C" void kernel_launch(void* const* d_in, const int* in_sizes, int n_in,
                              void* d_out, int out_size) {
    const float* X     = (const float*)d_in[0];  // [1024, 512]
    const float* W     = (const float*)d_in[1];  // [256, 1, 512]
    const float* diags = (const float*)d_in[2];  // [256, 512]
    const float* lower = (const float*)d_in[3];  // [256, 130816]
    float* out = (float*)d_out;                  // [1024, 256]

    build_Lh<<<(KC * D * 64) / 256, 256>>>(diags, lower);
    build_Xh<<<(1024 * D / 4) / 256, 256>>>(X);
    build_wL<<<dim3(KC, 2), 256>>>(W);

    cudaFuncSetAttribute(gml2_mma, cudaFuncAttributeMaxDynamicSharedMemorySize,
                         SMEMSZ);
    dim3 grid(8, KC, 4);
    gml2_mma<<<grid, 256, SMEMSZ>>>();

    finalize<<<1024, 256>>>(out);
}

// round 11
// speedup vs baseline: 1.0245x; 1.0245x over previous
#include <cuda_runtime.h>
#include <cuda_fp16.h>
#include <math.h>
#include <stdint.h>

#define KC   256
#define D    512
#define NLOW 130816

// Dense L in fp16, natural orientation: g_Lh[k][d][e] = L_k[d][e].
__device__ __half g_Lh[(size_t)KC * D * D];
// X in fp16.
__device__ __half g_Xh[(size_t)1024 * D];
// wL[k][e] = sum_d w_k[d] * Lh_k[d][e]  (fp32)
__device__ float g_wL[(size_t)KC * D];

__device__ __forceinline__ uint32_t smem_u32(const void* p) {
    uint32_t a;
    asm("{ .reg .u64 t; cvta.to.shared.u64 t, %1; cvt.u32.u64 %0, t; }"
        : "=r"(a) : "l"(p));
    return a;
}
__device__ __forceinline__ void cpasync16(uint32_t dst, const void* src) {
    asm volatile("cp.async.cg.shared.global [%0], [%1], 16;"
                 :: "r"(dst), "l"(src) : "memory");
}
#define LDSM4(r0, r1, r2, r3, addr) \
    asm volatile("ldmatrix.sync.aligned.m8n8.x4.shared.b16 {%0,%1,%2,%3}, [%4];" \
                 : "=r"(r0), "=r"(r1), "=r"(r2), "=r"(r3) : "r"(addr))
#define LDSM4T(r0, r1, r2, r3, addr) \
    asm volatile("ldmatrix.sync.aligned.m8n8.x4.trans.shared.b16 {%0,%1,%2,%3}, [%4];" \
                 : "=r"(r0), "=r"(r1), "=r"(r2), "=r"(r3) : "r"(addr))

// ---------------------------------------------------------------------------
// build_Lh: streaming expansion of packed L into fp16 [k][d][e], MLP=8.
// ---------------------------------------------------------------------------
__global__ void __launch_bounds__(256)
build_Lh(const float* __restrict__ diags, const float* __restrict__ lower) {
    const size_t i = (size_t)blockIdx.x * 256 + threadIdx.x;  // KC*D*64
    const int ep = ((int)(i & 63)) << 3;         // e..e+7
    const size_t kd = i >> 6;                    // k*D + d
    const int d  = (int)(kd & 511);
    const int kk = (int)(kd >> 9);
    if (d < ((ep >> 7) << 7)) return;            // never-read region
    const float* rowp = lower + (size_t)kk * NLOW + (((size_t)d * (d - 1)) >> 1);
    float v[8];
#pragma unroll
    for (int t = 0; t < 8; ++t) {
        const int e = ep + t;
        v[t] = (e < d) ? rowp[e] : 0.f;
    }
    if (d >= ep && d < ep + 8) { float t = diags[kd]; v[d - ep] = t * t; }
    uint4 u;
    __half2 h;
    h = __floats2half2_rn(v[0], v[1]); u.x = *(uint32_t*)&h;
    h = __floats2half2_rn(v[2], v[3]); u.y = *(uint32_t*)&h;
    h = __floats2half2_rn(v[4], v[5]); u.z = *(uint32_t*)&h;
    h = __floats2half2_rn(v[6], v[7]); u.w = *(uint32_t*)&h;
    *(uint4*)((char*)g_Lh + (kd * D + ep) * 2) = u;
}

// ---------------------------------------------------------------------------
__global__ void __launch_bounds__(256)
build_Xh(const float* __restrict__ X) {
    const int i = (blockIdx.x * 256 + threadIdx.x) * 4;   // 1024*512
    float4 x = *(const float4*)&X[i];
    __half2 h0 = __floats2half2_rn(x.x, x.y);
    __half2 h1 = __floats2half2_rn(x.z, x.w);
    *(uint2*)((char*)g_Xh + i * 2) = make_uint2(*(uint32_t*)&h0, *(uint32_t*)&h1);
}

// ---------------------------------------------------------------------------
__global__ void __launch_bounds__(512)
build_wL(const float* __restrict__ W) {
    __shared__ float ws[512];
    const int k = blockIdx.x, e = threadIdx.x;
    ws[e] = W[(size_t)k * D + e];
    __syncthreads();
    const __half* Lk = g_Lh + (size_t)k * D * D;
    float s = 0.f;
    const int dstart = (e >> 7) << 7;
#pragma unroll 4
    for (int d = dstart; d < D; ++d)
        s += ws[d] * __half2float(Lk[(size_t)d * D + e]);
    g_wL[(size_t)k * D + e] = s;
}

// ---------------------------------------------------------------------------
// Main: per (b-tile, k) CTA walks all 4 e-blocks (20 K-chunks of 64) with one
// continuous 3-stage cp.async pipeline. Per-j fold of (Q - wL)^2 into register
// row-totals; single epilogue writes sqrt to out. No partial buffers.
// A stage: 128x64 halfs stride 144 B; B stage: 64x128 halfs stride 272 B.
// ---------------------------------------------------------------------------
#define ROFF   0
#define WLOFF  1024
#define STG0   3072
#define ASZ    18432                          /* 128 * 144 */
#define BSZ    17408                          /* 64 * 272 */
#define STGSZ  (ASZ + BSZ)                    /* 35840 */
#define SMEMSZ (STG0 + 3 * STGSZ)             /* 110592 */
#define NCH    20

__device__ __forceinline__ int chunk_j(int t) {
    return (t < 8) ? 0 : (t < 14) ? 1 : (t < 18) ? 2 : 3;
}
__device__ __forceinline__ int chunk_base(int jj) {
    return (jj == 0) ? 0 : (jj == 1) ? 8 : (jj == 2) ? 14 : 18;
}

__global__ void __launch_bounds__(256, 2)
gml2_mma(float* __restrict__ out) {
    extern __shared__ char smem[];
    const int tid = threadIdx.x;
    const int wid = tid >> 5, lid = tid & 31;
    const int b0 = blockIdx.x * 128;
    const int k  = blockIdx.y;

    const uint32_t sbase = smem_u32(smem);
    float* wLs = (float*)(smem + WLOFF);
    wLs[tid]       = g_wL[(size_t)k * D + tid];
    wLs[tid + 256] = g_wL[(size_t)k * D + 256 + tid];

    const __half* Bk = g_Lh + (size_t)k * D * D;   // [d][e]
    const __half* Ab = g_Xh + (size_t)b0 * D;

#define ISSUE_CHUNK(tt, st) do {                                            \
        const int jj_ = chunk_j(tt);                                       \
        const int e0_ = jj_ << 7;                                          \
        const int d0_ = e0_ + ((tt) - chunk_base(jj_)) * 64;               \
        const uint32_t as_ = sbase + STG0 + (st) * STGSZ;                   \
        const uint32_t bs_ = as_ + ASZ;                                     \
        _Pragma("unroll")                                                   \
        for (int it = 0; it < 4; ++it) {  /* A: 128 rows x 8 segs */        \
            const int idx = it * 256 + tid;                                 \
            const int row = idx >> 3, seg = idx & 7;                        \
            cpasync16(as_ + row * 144 + seg * 16,                           \
                      Ab + (size_t)row * D + d0_ + seg * 8);                \
        }                                                                   \
        _Pragma("unroll")                                                   \
        for (int it = 0; it < 4; ++it) {  /* B: 64 rows x 16 segs */        \
            const int idx = it * 256 + tid;                                 \
            const int rl = idx >> 4, seg = idx & 15;                        \
            cpasync16(bs_ + rl * 272 + seg * 16,                            \
                      Bk + (size_t)(d0_ + rl) * D + e0_ + seg * 8);         \
        }                                                                   \
    } while (0)

    // ---- prologue: issue chunks 0,1
    ISSUE_CHUNK(0, 0);
    asm volatile("cp.async.commit_group;" ::: "memory");
    ISSUE_CHUNK(1, 1);
    asm volatile("cp.async.commit_group;" ::: "memory");

    float acc[2][8][4];
#pragma unroll
    for (int mt = 0; mt < 2; ++mt)
#pragma unroll
        for (int nt = 0; nt < 8; ++nt)
#pragma unroll
            for (int q2 = 0; q2 < 4; ++q2) acc[mt][nt][q2] = 0.f;
    float q[4] = {0.f, 0.f, 0.f, 0.f};

    const int m0 = (wid & 3) * 32, n0 = (wid >> 2) * 64;
    const int gq = lid >> 2, tg = lid & 3;
    const uint32_t aL = sbase + STG0 + (m0 + (lid & 15)) * 144 + (lid >> 4) * 16;
    const uint32_t bL = sbase + STG0 + ASZ +
                        (lid & 15) * 272 + (lid >> 4) * 16 + n0 * 2;

#pragma unroll 1
    for (int t = 0; t < NCH; ++t) {
        const int st = t % 3;
        const int jj = chunk_j(t);
        const int cl = t - chunk_base(jj);

        asm volatile("cp.async.wait_group 1;" ::: "memory");
        __syncthreads();

        if (t + 2 < NCH) ISSUE_CHUNK(t + 2, (st + 2 >= 3) ? st - 1 : st + 2);
        asm volatile("cp.async.commit_group;" ::: "memory");

        // ---- compute chunk t; triangular warp skip (first chunk, upper half)
        if (!(n0 == 64 && cl == 0)) {
            const uint32_t aB = aL + st * STGSZ;
            const uint32_t bB = bL + st * STGSZ;
#pragma unroll
            for (int ks = 0; ks < 4; ++ks) {
                uint32_t a[2][4], b[8][2];
#pragma unroll
                for (int mt = 0; mt < 2; ++mt)
                    LDSM4(a[mt][0], a[mt][1], a[mt][2], a[mt][3],
                          aB + mt * (16 * 144) + ks * 32);
#pragma unroll
                for (int nt2 = 0; nt2 < 4; ++nt2)
                    LDSM4T(b[nt2 * 2][0], b[nt2 * 2][1],
                           b[nt2 * 2 + 1][0], b[nt2 * 2 + 1][1],
                           bB + ks * (16 * 272) + nt2 * 32);
#pragma unroll
                for (int mt = 0; mt < 2; ++mt)
#pragma unroll
                    for (int nt = 0; nt < 8; ++nt)
                        asm volatile(
                            "mma.sync.aligned.m16n8k16.row.col.f32.f16.f16.f32 "
                            "{%0,%1,%2,%3},{%4,%5,%6,%7},{%8,%9},{%0,%1,%2,%3};"
                            : "+f"(acc[mt][nt][0]), "+f"(acc[mt][nt][1]),
                              "+f"(acc[mt][nt][2]), "+f"(acc[mt][nt][3])
                            : "r"(a[mt][0]), "r"(a[mt][1]),
                              "r"(a[mt][2]), "r"(a[mt][3]),
                              "r"(b[nt][0]), "r"(b[nt][1]));
            }
        }

        // ---- at e-block end: fold (acc - wL)^2 into q, reset acc (no sync)
        if (t == 7 || t == 13 || t == 17 || t == 19) {
            const int e0 = jj << 7;
#pragma unroll
            for (int mt = 0; mt < 2; ++mt) {
                float s0 = 0.f, s1 = 0.f;
#pragma unroll
                for (int nt = 0; nt < 8; ++nt) {
                    const int c0 = e0 + n0 + nt * 8 + tg * 2;
                    const float wl0 = wLs[c0], wl1 = wLs[c0 + 1];
                    float p0 = acc[mt][nt][0] - wl0;
                    float p1 = acc[mt][nt][1] - wl1;
                    float p2 = acc[mt][nt][2] - wl0;
                    float p3 = acc[mt][nt][3] - wl1;
                    s0 += p0 * p0 + p1 * p1;
                    s1 += p2 * p2 + p3 * p3;
                    acc[mt][nt][0] = 0.f; acc[mt][nt][1] = 0.f;
                    acc[mt][nt][2] = 0.f; acc[mt][nt][3] = 0.f;
                }
                q[mt * 2 + 0] += s0;   // row m0 + 16*mt + gq
                q[mt * 2 + 1] += s1;   // row m0 + 16*mt + gq + 8
            }
        }
    }
#undef ISSUE_CHUNK

    // ---- final reduce + output
#pragma unroll
    for (int i = 0; i < 4; ++i) {
        q[i] += __shfl_xor_sync(0xffffffffu, q[i], 1);
        q[i] += __shfl_xor_sync(0xffffffffu, q[i], 2);
    }
    float* red = (float*)(smem + ROFF);
    __syncthreads();
    if (tg == 0) {
        const int wn = wid >> 2;
        const int rr = m0 + gq;
        red[wn * 128 + rr +  0] = q[0];
        red[wn * 128 + rr +  8] = q[1];
        red[wn * 128 + rr + 16] = q[2];
        red[wn * 128 + rr + 24] = q[3];
    }
    __syncthreads();
    if (tid < 128) {
        float s = red[tid] + red[128 + tid];
        out[(size_t)(b0 + tid) * KC + k] = sqrtf(s);
    }
}

// ---------------------------------------------------------------------------
extern "C" void kernel_launch(void* const* d_in, const int* in_sizes, int n_in,
                              void* d_out, int out_size) {
    const float* X     = (const float*)d_in[0];  // [1024, 512]
    const float* W     = (const float*)d_in[1];  // [256, 1, 512]
    const float* diags = (const float*)d_in[2];  // [256, 512]
    const float* lower = (const float*)d_in[3];  // [256, 130816]
    float* out = (float*)d_out;                  // [1024, 256]

    build_Lh<<<(KC * D * 64) / 256, 256>>>(diags, lower);
    build_Xh<<<(1024 * D / 4) / 256, 256>>>(X);
    build_wL<<<KC, 512>>>(W);

    cudaFuncSetAttribute(gml2_mma, cudaFuncAttributeMaxDynamicSharedMemorySize,
                         SMEMSZ);
    dim3 grid(8, KC);
    gml2_mma<<<grid, 256, SMEMSZ>>>(out);
}

// round 12
// speedup vs baseline: 1.0664x; 1.0409x over previous
#include <cuda_runtime.h>
#include <cuda_fp16.h>
#include <math.h>
#include <stdint.h>

#define KC   256
#define D    512
#define NLOW 130816

// Dense L in fp16, natural orientation: g_Lh[k][d][e] = L_k[d][e].
__device__ __half g_Lh[(size_t)KC * D * D];
// X in fp16.
__device__ __half g_Xh[(size_t)1024 * D];
// wL[k][e] = sum_d w_k[d] * Lh_k[d][e]  (fp32)
__device__ float g_wL[(size_t)KC * D];
// Per-e-block partial squared sums: g_part[j][b][k]
__device__ float g_part[(size_t)4 * 1024 * KC];

__device__ __forceinline__ uint32_t smem_u32(const void* p) {
    uint32_t a;
    asm("{ .reg .u64 t; cvta.to.shared.u64 t, %1; cvt.u32.u64 %0, t; }"
        : "=r"(a) : "l"(p));
    return a;
}
__device__ __forceinline__ void cpasync16(uint32_t dst, const void* src) {
    asm volatile("cp.async.cg.shared.global [%0], [%1], 16;"
                 :: "r"(dst), "l"(src) : "memory");
}
#define LDSM4(r0, r1, r2, r3, addr) \
    asm volatile("ldmatrix.sync.aligned.m8n8.x4.shared.b16 {%0,%1,%2,%3}, [%4];" \
                 : "=r"(r0), "=r"(r1), "=r"(r2), "=r"(r3) : "r"(addr))
#define LDSM4T(r0, r1, r2, r3, addr) \
    asm volatile("ldmatrix.sync.aligned.m8n8.x4.trans.shared.b16 {%0,%1,%2,%3}, [%4];" \
                 : "=r"(r0), "=r"(r1), "=r"(r2), "=r"(r3) : "r"(addr))

// ---------------------------------------------------------------------------
// build_Lh: streaming expansion of packed L into fp16 [k][d][e], MLP=8.
// ---------------------------------------------------------------------------
__global__ void __launch_bounds__(256)
build_Lh(const float* __restrict__ diags, const float* __restrict__ lower) {
    const size_t i = (size_t)blockIdx.x * 256 + threadIdx.x;  // KC*D*64
    const int ep = ((int)(i & 63)) << 3;         // e..e+7
    const size_t kd = i >> 6;                    // k*D + d
    const int d  = (int)(kd & 511);
    const int kk = (int)(kd >> 9);
    if (d < ((ep >> 7) << 7)) return;            // never-read region
    const float* rowp = lower + (size_t)kk * NLOW + (((size_t)d * (d - 1)) >> 1);
    float v[8];
#pragma unroll
    for (int t = 0; t < 8; ++t) {
        const int e = ep + t;
        v[t] = (e < d) ? rowp[e] : 0.f;
    }
    if (d >= ep && d < ep + 8) { float t = diags[kd]; v[d - ep] = t * t; }
    uint4 u;
    __half2 h;
    h = __floats2half2_rn(v[0], v[1]); u.x = *(uint32_t*)&h;
    h = __floats2half2_rn(v[2], v[3]); u.y = *(uint32_t*)&h;
    h = __floats2half2_rn(v[4], v[5]); u.z = *(uint32_t*)&h;
    h = __floats2half2_rn(v[6], v[7]); u.w = *(uint32_t*)&h;
    *(uint4*)((char*)g_Lh + (kd * D + ep) * 2) = u;
}

// ---------------------------------------------------------------------------
__global__ void __launch_bounds__(256)
build_Xh(const float* __restrict__ X) {
    const int i = (blockIdx.x * 256 + threadIdx.x) * 4;   // 1024*512
    float4 x = *(const float4*)&X[i];
    __half2 h0 = __floats2half2_rn(x.x, x.y);
    __half2 h1 = __floats2half2_rn(x.z, x.w);
    *(uint2*)((char*)g_Xh + i * 2) = make_uint2(*(uint32_t*)&h0, *(uint32_t*)&h1);
}

// ---------------------------------------------------------------------------
__global__ void __launch_bounds__(512)
build_wL(const float* __restrict__ W) {
    __shared__ float ws[512];
    const int k = blockIdx.x, e = threadIdx.x;
    ws[e] = W[(size_t)k * D + e];
    __syncthreads();
    const __half* Lk = g_Lh + (size_t)k * D * D;
    float s = 0.f;
    const int dstart = (e >> 7) << 7;
#pragma unroll 4
    for (int d = dstart; d < D; ++d)
        s += ws[d] * __half2float(Lk[(size_t)d * D + e]);
    g_wL[(size_t)k * D + e] = s;
}

// ---------------------------------------------------------------------------
// Main GEMM: Q = Xh @ Lh block; epilogue squares (Q - wL[e]) and row-reduces.
// K-chunks of 64, 3 SMEM stages, one cp.async group per chunk, wait_group 1.
// A stage: 128x64 halfs stride 144 B; B stage: 64x128 halfs stride 272 B.
// Odd warps run the ks-steps rotated by 2 so LDSM bursts of half the warps
// overlap HMMA issue of the other half (crossbar/tensor phase interleave).
// ---------------------------------------------------------------------------
#define ROFF   0
#define WLOFF  2048
#define STG0   2560
#define ASZ    18432                          /* 128 * 144 */
#define BSZ    17408                          /* 64 * 272 */
#define STGSZ  (ASZ + BSZ)                    /* 35840 */
#define SMEMSZ (2560 + 3 * 35840)             /* 110080 */

__global__ void __launch_bounds__(256, 2)
gml2_mma() {
    extern __shared__ char smem[];
    const int tid = threadIdx.x;
    const int wid = tid >> 5, lid = tid & 31;
    const int b0 = blockIdx.x * 128;
    const int k  = blockIdx.y;
    const int j  = blockIdx.z;
    const int e0 = j << 7;
    const int nc = 8 - (j << 1);              // K-chunks of 64: d in [e0, 512)

    const uint32_t sbase = smem_u32(smem);
    float* wLs = (float*)(smem + WLOFF);
    if (tid < 128) wLs[tid] = g_wL[(size_t)k * D + e0 + tid];

    const __half* Bk = g_Lh + (size_t)k * D * D;   // [d][e]
    const __half* Ab = g_Xh + (size_t)b0 * D;

#define ISSUE_CHUNK(cc, st) do {                                            \
        const int d0_ = e0 + (cc) * 64;                                     \
        const uint32_t as_ = sbase + STG0 + (st) * STGSZ;                   \
        const uint32_t bs_ = as_ + ASZ;                                     \
        _Pragma("unroll")                                                   \
        for (int it = 0; it < 4; ++it) {  /* A: 128 rows x 8 segs */        \
            const int idx = it * 256 + tid;                                 \
            const int row = idx >> 3, seg = idx & 7;                        \
            cpasync16(as_ + row * 144 + seg * 16,                           \
                      Ab + (size_t)row * D + d0_ + seg * 8);                \
        }                                                                   \
        _Pragma("unroll")                                                   \
        for (int it = 0; it < 4; ++it) {  /* B: 64 rows x 16 segs */        \
            const int idx = it * 256 + tid;                                 \
            const int rl = idx >> 4, seg = idx & 15;                        \
            cpasync16(bs_ + rl * 272 + seg * 16,                            \
                      Bk + (size_t)(d0_ + rl) * D + e0 + seg * 8);          \
        }                                                                   \
    } while (0)

    // ---- prologue: issue chunks 0,1
    ISSUE_CHUNK(0, 0);
    asm volatile("cp.async.commit_group;" ::: "memory");
    if (nc > 1) ISSUE_CHUNK(1, 1);
    asm volatile("cp.async.commit_group;" ::: "memory");

    float acc[2][8][4];
#pragma unroll
    for (int mt = 0; mt < 2; ++mt)
#pragma unroll
        for (int nt = 0; nt < 8; ++nt)
#pragma unroll
            for (int q = 0; q < 4; ++q) acc[mt][nt][q] = 0.f;

    const int m0 = (wid & 3) * 32, n0 = (wid >> 2) * 64;
    const int krot = (wid & 1) << 1;          // ks phase stagger: 0 or 2
    const uint32_t aL = sbase + STG0 + (m0 + (lid & 15)) * 144 + (lid >> 4) * 16;
    const uint32_t bL = sbase + STG0 + ASZ +
                        (lid & 15) * 272 + (lid >> 4) * 16 + n0 * 2;

    int st = 0;
    for (int c = 0; c < nc; ++c) {
        asm volatile("cp.async.wait_group 1;" ::: "memory");
        __syncthreads();

        if (c + 2 < nc) {
            const int st2 = (st + 2 >= 3) ? st - 1 : st + 2;
            ISSUE_CHUNK(c + 2, st2);
        }
        asm volatile("cp.async.commit_group;" ::: "memory");

        // ---- compute chunk c; triangular warp skip (chunk 0, upper half)
        if (!(n0 == 64 && c == 0)) {
            const uint32_t aB = aL + st * STGSZ;
            const uint32_t bB = bL + st * STGSZ;
#pragma unroll
            for (int ks0 = 0; ks0 < 4; ++ks0) {
                const int ks = ks0 ^ krot;    // phase-staggered K-step order
                uint32_t a[2][4], b[8][2];
#pragma unroll
                for (int mt = 0; mt < 2; ++mt)
                    LDSM4(a[mt][0], a[mt][1], a[mt][2], a[mt][3],
                          aB + mt * (16 * 144) + ks * 32);
#pragma unroll
                for (int nt2 = 0; nt2 < 4; ++nt2)
                    LDSM4T(b[nt2 * 2][0], b[nt2 * 2][1],
                           b[nt2 * 2 + 1][0], b[nt2 * 2 + 1][1],
                           bB + ks * (16 * 272) + nt2 * 32);
#pragma unroll
                for (int mt = 0; mt < 2; ++mt)
#pragma unroll
                    for (int nt = 0; nt < 8; ++nt)
                        asm volatile(
                            "mma.sync.aligned.m16n8k16.row.col.f32.f16.f16.f32 "
                            "{%0,%1,%2,%3},{%4,%5,%6,%7},{%8,%9},{%0,%1,%2,%3};"
                            : "+f"(acc[mt][nt][0]), "+f"(acc[mt][nt][1]),
                              "+f"(acc[mt][nt][2]), "+f"(acc[mt][nt][3])
                            : "r"(a[mt][0]), "r"(a[mt][1]),
                              "r"(a[mt][2]), "r"(a[mt][3]),
                              "r"(b[nt][0]), "r"(b[nt][1]));
            }
        }
        st = (st == 2) ? 0 : st + 1;
    }
#undef ISSUE_CHUNK

    // ---- epilogue: subtract wL, square, row-reduce
    const int gq = lid >> 2, tg = lid & 3;
    float q[4];
#pragma unroll
    for (int mt = 0; mt < 2; ++mt) {
        float s0 = 0.f, s1 = 0.f;
#pragma unroll
        for (int nt = 0; nt < 8; ++nt) {
            const int c0 = n0 + nt * 8 + tg * 2;
            const float wl0 = wLs[c0], wl1 = wLs[c0 + 1];
            float p0 = acc[mt][nt][0] - wl0;
            float p1 = acc[mt][nt][1] - wl1;
            float p2 = acc[mt][nt][2] - wl0;
            float p3 = acc[mt][nt][3] - wl1;
            s0 += p0 * p0 + p1 * p1;
            s1 += p2 * p2 + p3 * p3;
        }
        q[mt * 2 + 0] = s0;   // row m0 + 16*mt + gq
        q[mt * 2 + 1] = s1;   // row m0 + 16*mt + gq + 8
    }
#pragma unroll
    for (int i = 0; i < 4; ++i) {
        q[i] += __shfl_xor_sync(0xffffffffu, q[i], 1);
        q[i] += __shfl_xor_sync(0xffffffffu, q[i], 2);
    }
    float* red = (float*)(smem + ROFF);
    __syncthreads();
    if (tg == 0) {
        const int wn = wid >> 2;
        const int rr = m0 + gq;
        red[wn * 128 + rr +  0] = q[0];
        red[wn * 128 + rr +  8] = q[1];
        red[wn * 128 + rr + 16] = q[2];
        red[wn * 128 + rr + 24] = q[3];
    }
    __syncthreads();
    if (tid < 128) {
        float s = red[tid] + red[128 + tid];
        g_part[((size_t)j * 1024 + b0 + tid) * KC + k] = s;
    }
}

// ---------------------------------------------------------------------------
__global__ void finalize(float* __restrict__ out) {
    const size_t idx = (size_t)blockIdx.x * 256 + threadIdx.x;  // 1024*256
    float s = g_part[idx] + g_part[262144 + idx] +
              g_part[2 * 262144 + idx] + g_part[3 * 262144 + idx];
    out[idx] = sqrtf(s);
}

// ---------------------------------------------------------------------------
extern "C" void kernel_launch(void* const* d_in, const int* in_sizes, int n_in,
                              void* d_out, int out_size) {
    const float* X     = (const float*)d_in[0];  // [1024, 512]
    const float* W     = (const float*)d_in[1];  // [256, 1, 512]
    const float* diags = (const float*)d_in[2];  // [256, 512]
    const float* lower = (const float*)d_in[3];  // [256, 130816]
    float* out = (float*)d_out;                  // [1024, 256]

    build_Lh<<<(KC * D * 64) / 256, 256>>>(diags, lower);
    build_Xh<<<(1024 * D / 4) / 256, 256>>>(X);
    build_wL<<<KC, 512>>>(W);

    cudaFuncSetAttribute(gml2_mma, cudaFuncAttributeMaxDynamicSharedMemorySize,
                         SMEMSZ);
    dim3 grid(8, KC, 4);
    gml2_mma<<<grid, 256, SMEMSZ>>>();

    finalize<<<1024, 256>>>(out);
}